// round 6
// baseline (speedup 1.0000x reference)
#include <cuda_runtime.h>
#include <math.h>

#define CIN 32
#define COUT 64
#define CC (CIN * COUT)
// Packed weight layout: [kd][kh][p(3)][cin][cout] of float2 (kw=2p, kw=2p+1; p=2 hi = 0)
#define NWP (5 * 5 * 3 * CC)

__device__ unsigned long long g_wt2[NWP];

typedef unsigned long long u64;

__global__ void wt_pack_kernel(const float* __restrict__ w) {
    int i = blockIdx.x * blockDim.x + threadIdx.x;
    if (i >= NWP) return;
    int cout = i & 63;
    int cin  = (i >> 6) & 31;
    int t    = i >> 11;            // kd*15 + kh*3 + p
    int p    = t % 3;
    int kh   = (t / 3) % 5;
    int kd   = t / 15;
    const float* src = w + (cin * COUT + cout) * 125 + kd * 25 + kh * 5;
    float lo = src[2 * p];
    float hi = (p < 2) ? src[2 * p + 1] : 0.f;
    g_wt2[i] = ((u64)__float_as_uint(hi) << 32) | (u64)__float_as_uint(lo);
}

__device__ __forceinline__ void fma2(u64& d, u64 a, u64 b) {
    asm("fma.rn.f32x2 %0, %1, %2, %0;" : "+l"(d) : "l"(a), "l"(b));
}

// One kh tap-row: 3 kw-pairs, rows (ra, rb, rc) = spatial rows jh, jh+1, jh+2.
__device__ __forceinline__ void kh_tap(const u64* __restrict__ wp,
                                       const u64 ra[5], const u64 rb[5], const u64 rc[5],
                                       const int ph, u64 acc[6][3])
{
#pragma unroll
    for (int p = 0; p < 3; ++p) {
        const int jw = 2 - p;
        const u64 w2 = __ldg(wp + p * CC);
#pragma unroll
        for (int i = 0; i < 3; ++i) {
            fma2(acc[ph + 0][i], w2, ra[jw + i]);
            fma2(acc[ph + 2][i], w2, rb[jw + i]);
            fma2(acc[ph + 4][i], w2, rc[jw + i]);
        }
    }
}

// One kd tap-plane with a rolling 3-row register window (15 u64 live for s).
__device__ __forceinline__ void process_kd(
    const int kd, const int l_d, const u64* __restrict__ sp_base,
    const u64* __restrict__ wp_cin, u64 acc[6][3])
{
    const int id_l = (l_d + 4 - kd) >> 1;               // in [0,4]
    const u64* sp = sp_base + id_l * 25;
    const u64* wp = wp_cin + (kd * 15) * CC;

    u64 sa[5], sb[5], sc[5];
#pragma unroll
    for (int q = 0; q < 5; ++q) sa[q] = sp[10 + q];     // row 2
#pragma unroll
    for (int q = 0; q < 5; ++q) sb[q] = sp[15 + q];     // row 3
#pragma unroll
    for (int q = 0; q < 5; ++q) sc[q] = sp[20 + q];     // row 4

    kh_tap(wp + 0 * 3 * CC, sa, sb, sc, 0, acc);        // kh=0, jh=2
    kh_tap(wp + 1 * 3 * CC, sa, sb, sc, 1, acc);        // kh=1, jh=2

#pragma unroll
    for (int q = 0; q < 5; ++q) sc[q] = sp[5 + q];      // row 1 (replaces row 4)

    kh_tap(wp + 2 * 3 * CC, sc, sa, sb, 0, acc);        // kh=2, jh=1
    kh_tap(wp + 3 * 3 * CC, sc, sa, sb, 1, acc);        // kh=3, jh=1

#pragma unroll
    for (int q = 0; q < 5; ++q) sb[q] = sp[q];          // row 0 (replaces row 3)

    kh_tap(wp + 4 * 3 * CC, sb, sc, sa, 0, acc);        // kh=4, jh=0
}

__global__ __launch_bounds__(384, 2)
void fused_kernel(const float* __restrict__ x,
                  const float* __restrict__ bias,
                  float* __restrict__ out)
{
    __shared__ u64   xs2[CIN * 125];      // input patch duplicated (v,v)
    __shared__ float red[6 * 64 + 2];

    const int b   = blockIdx.x;           // 8000 = 16 * 5 * 10 * 10
    const int n   = b / 500;
    const int r   = b % 500;
    const int odc = r / 100;
    const int ohc = (r / 10) % 10;
    const int owc = r % 10;

    const int tid  = threadIdx.x;         // 384 threads = 12 warps
    const int wid  = tid >> 5;
    const int lane = tid & 31;
    // SMSP-balancing permutation: each SMSP gets a mix of even/odd parity warps.
    const int p_   = wid >> 1;
    const int l_d  = ((p_ & 1) ? 3 : 0) + (p_ >> 1);
    const int cout = ((wid & 1) << 5) | lane;

    const int id0 = 3 * odc - 1;
    const int ih0 = 3 * ohc - 1;
    const int iw0 = 3 * owc - 1;

    for (int t = tid; t < CIN * 125; t += 384) {
        const int cin = t / 125;
        const int rr  = t % 125;
        const int dl  = rr / 25;
        const int hl  = (rr / 5) % 5;
        const int wl  = rr % 5;
        const int id = id0 + dl, ih = ih0 + hl, iw = iw0 + wl;
        float v = 0.f;
        if (id >= 0 && ih >= 0 && iw >= 0)     // upper bounds always in range
            v = x[(((n * CIN + cin) * 16 + id) << 10) + (ih << 5) + iw];
        const u64 bv = (u64)__float_as_uint(v);
        xs2[t] = (bv << 32) | bv;
    }
    __syncthreads();

    u64 acc[6][3];
#pragma unroll
    for (int a = 0; a < 6; ++a)
#pragma unroll
        for (int c = 0; c < 3; ++c) acc[a][c] = 0ull;

    if (!(l_d & 1)) {
#pragma unroll 1
        for (int cin = 0; cin < CIN; ++cin) {
            const u64* sp_base = xs2 + cin * 125;
            const u64* wp_cin  = g_wt2 + cin * COUT + cout;
            process_kd(0, l_d, sp_base, wp_cin, acc);
            process_kd(2, l_d, sp_base, wp_cin, acc);
            process_kd(4, l_d, sp_base, wp_cin, acc);
        }
    } else {
#pragma unroll 1
        for (int cin = 0; cin < CIN; ++cin) {
            const u64* sp_base = xs2 + cin * 125;
            const u64* wp_cin  = g_wt2 + cin * COUT + cout;
            process_kd(1, l_d, sp_base, wp_cin, acc);
            process_kd(3, l_d, sp_base, wp_cin, acc);
        }
    }

    // max over this thread's 6x6 (oh,ow) slab (unpack f32x2 pairs)
    float m = -INFINITY;
#pragma unroll
    for (int a = 0; a < 6; ++a)
#pragma unroll
        for (int c = 0; c < 3; ++c) {
            m = fmaxf(m, __uint_as_float((unsigned)(acc[a][c] & 0xffffffffu)));
            m = fmaxf(m, __uint_as_float((unsigned)(acc[a][c] >> 32)));
        }

    red[l_d * 64 + cout] = m;
    __syncthreads();

    if (tid < 64) {
        float v = red[tid];
#pragma unroll
        for (int l = 1; l < 6; ++l) v = fmaxf(v, red[l * 64 + tid]);
        v += bias[tid];
#pragma unroll
        for (int o = 16; o > 0; o >>= 1)
            v += __shfl_down_sync(0xffffffffu, v, o);
        if ((tid & 31) == 0) red[6 * 64 + (tid >> 5)] = v;
    }
    __syncthreads();
    if (tid == 0) out[b] = red[6 * 64] + red[6 * 64 + 1];
}

extern "C" void kernel_launch(void* const* d_in, const int* in_sizes, int n_in,
                              void* d_out, int out_size) {
    const float* x    = (const float*)d_in[0];
    const float* w    = (const float*)d_in[1];
    const float* bias = (const float*)d_in[2];
    float* out = (float*)d_out;

    wt_pack_kernel<<<(NWP + 255) / 256, 256>>>(w);
    fused_kernel<<<8000, 384>>>(x, bias, out);
}

// round 7
// speedup vs baseline: 2.4397x; 2.4397x over previous
#include <cuda_runtime.h>
#include <math.h>

#define CIN 32
#define COUT 64

// Weight B-fragments prepacked in mma.m16n8k8 layout:
// [tap(125)][kc(4)][ntp(4)][lane(32)] uint4 = (b0@nt even, b1@nt even, b0@nt odd, b1@nt odd)
__device__ uint4 g_bf[125 * 4 * 4 * 32];

__device__ __forceinline__ unsigned f2tf32(float v) {
    unsigned u;
    asm("cvt.rna.tf32.f32 %0, %1;" : "=r"(u) : "f"(v));
    return u;
}

__global__ void bf_pack_kernel(const float* __restrict__ w) {
    int i = blockIdx.x * blockDim.x + threadIdx.x;
    if (i >= 125 * 4 * 4 * 32) return;
    int lane = i & 31, ntp = (i >> 5) & 3, kc = (i >> 7) & 3, tap = i >> 9;
    int k = lane & 3, n = lane >> 2;
    int cinA = kc * 8 + k, cinB = cinA + 4;
    int cout0 = (2 * ntp) * 8 + n, cout1 = cout0 + 8;
    uint4 o;
    o.x = f2tf32(w[(cinA * COUT + cout0) * 125 + tap]);
    o.y = f2tf32(w[(cinB * COUT + cout0) * 125 + tap]);
    o.z = f2tf32(w[(cinA * COUT + cout1) * 125 + tap]);
    o.w = f2tf32(w[(cinB * COUT + cout1) * 125 + tap]);
    g_bf[i] = o;
}

#define MMA(c0, c1, c2, c3, a0, a1, a2, a3, b0, b1)                              \
    asm("mma.sync.aligned.m16n8k8.row.col.f32.tf32.tf32.f32 "                    \
        "{%0,%1,%2,%3}, {%4,%5,%6,%7}, {%8,%9}, {%0,%1,%2,%3};"                  \
        : "+f"(c0), "+f"(c1), "+f"(c2), "+f"(c3)                                 \
        : "r"(a0), "r"(a1), "r"(a2), "r"(a3), "r"(b0), "r"(b1))

__device__ __forceinline__ int qoff(int pos) {      // pos in [0,27)
    int qd = pos / 9, qh = (pos / 3) % 3, qw = pos % 3;
    return qd * 25 + qh * 5 + qw;
}

__global__ __launch_bounds__(128, 5)
void fused_kernel(const float* __restrict__ x,
                  const float* __restrict__ bias,
                  float* __restrict__ out)
{
    __shared__ float xs[CIN * 125];     // tf32-rounded patch [cin][5][5][5]
    __shared__ float smax[4][64];
    __shared__ float ssum[64];

    const int b   = blockIdx.x;         // 8000 = 16 * 5 * 10 * 10
    const int n_  = b / 500;
    const int r_  = b % 500;
    const int odc = r_ / 100;
    const int ohc = (r_ / 10) % 10;
    const int owc = r_ % 10;

    const int tid  = threadIdx.x;       // 128 threads = 4 warps
    const int wid  = tid >> 5;
    const int lane = tid & 31;
    const int kb   = lane & 3;          // k-group
    const int rr   = lane >> 2;         // row-group

    const int id0 = 3 * odc - 1;
    const int ih0 = 3 * ohc - 1;
    const int iw0 = 3 * owc - 1;

    // Stage patch (tf32-rounded), zero-fill the -1 halo.
    for (int t = tid; t < CIN * 125; t += 128) {
        const int cin = t / 125;
        const int rm  = t % 125;
        const int dl  = rm / 25, hl = (rm / 5) % 5, wl = rm % 5;
        const int id = id0 + dl, ih = ih0 + hl, iw = iw0 + wl;
        float v = 0.f;
        if (id >= 0 && ih >= 0 && iw >= 0)
            v = x[(((n_ * CIN + cin) * 16 + id) << 10) + (ih << 5) + iw];
        xs[t] = __uint_as_float(f2tf32(v));
    }
    __syncthreads();

    const int base0 = kb * 125;         // cin lane offset (floats)

    float rmax[8][2];
#pragma unroll
    for (int nt = 0; nt < 8; ++nt) { rmax[nt][0] = -INFINITY; rmax[nt][1] = -INFINITY; }

    const int KD[2][3] = {{4, 2, 0}, {3, 1, 0}};
    const int NK[2]    = {3, 2};

#pragma unroll 1
    for (int s = 0; s < 4; ++s) {
        const int mi   = s * 4 + wid;   // 16 m-tiles: [class(8)][half(2)]
        const int cls  = mi >> 1;
        const int half = mi & 1;
        const int pd = (cls >> 2) & 1, ph = (cls >> 1) & 1, pw = cls & 1;

        const int pos0 = half * 16 + rr;        // always < 27
        const int pos1 = pos0 + 8;
        const bool v1  = (pos1 < 27);
        const int q0 = qoff(pos0);
        const int q1 = v1 ? qoff(pos1) : 0;

        float c[8][4];
#pragma unroll
        for (int nt = 0; nt < 8; ++nt)
#pragma unroll
            for (int j = 0; j < 4; ++j) c[nt][j] = 0.f;

#pragma unroll 1
        for (int ia = 0; ia < NK[pd]; ++ia) {
            const int kd = KD[pd][ia], jd = 2 - (kd >> 1);
#pragma unroll 1
            for (int ib = 0; ib < NK[ph]; ++ib) {
                const int kh = KD[ph][ib], jh = 2 - (kh >> 1);
#pragma unroll 1
                for (int ic = 0; ic < NK[pw]; ++ic) {
                    const int kw = KD[pw][ic], jw = 2 - (kw >> 1);
                    const int tap  = kd * 25 + kh * 5 + kw;
                    const int jofs = jd * 25 + jh * 5 + jw;
                    const uint4* bp = g_bf + (tap * 16) * 32 + lane;
#pragma unroll
                    for (int kc = 0; kc < 4; ++kc) {
                        const int ab = kc * 1000 + base0 + jofs;
                        const unsigned a0 = __float_as_uint(xs[ab + q0]);
                        const unsigned a1 = __float_as_uint(xs[ab + q1]);
                        const unsigned a2 = __float_as_uint(xs[ab + 500 + q0]);
                        const unsigned a3 = __float_as_uint(xs[ab + 500 + q1]);
#pragma unroll
                        for (int ntp = 0; ntp < 4; ++ntp) {
                            const uint4 B = bp[(kc * 4 + ntp) * 32];
                            MMA(c[2 * ntp][0], c[2 * ntp][1], c[2 * ntp][2], c[2 * ntp][3],
                                a0, a1, a2, a3, B.x, B.y);
                            MMA(c[2 * ntp + 1][0], c[2 * ntp + 1][1], c[2 * ntp + 1][2], c[2 * ntp + 1][3],
                                a0, a1, a2, a3, B.z, B.w);
                        }
                    }
                }
            }
        }

        // fold max-pool over this m-tile's positions (mask padded rows)
#pragma unroll
        for (int nt = 0; nt < 8; ++nt) {
            rmax[nt][0] = fmaxf(rmax[nt][0], c[nt][0]);
            rmax[nt][1] = fmaxf(rmax[nt][1], c[nt][1]);
            if (v1) {
                rmax[nt][0] = fmaxf(rmax[nt][0], c[nt][2]);
                rmax[nt][1] = fmaxf(rmax[nt][1], c[nt][3]);
            }
        }
    }

    // reduce max across row-groups (lanes sharing kb)
#pragma unroll
    for (int o = 4; o < 32; o <<= 1)
#pragma unroll
        for (int nt = 0; nt < 8; ++nt) {
            rmax[nt][0] = fmaxf(rmax[nt][0], __shfl_xor_sync(0xffffffffu, rmax[nt][0], o));
            rmax[nt][1] = fmaxf(rmax[nt][1], __shfl_xor_sync(0xffffffffu, rmax[nt][1], o));
        }
    if (rr == 0) {
#pragma unroll
        for (int nt = 0; nt < 8; ++nt) {
            smax[wid][nt * 8 + 2 * kb]     = rmax[nt][0];
            smax[wid][nt * 8 + 2 * kb + 1] = rmax[nt][1];
        }
    }
    __syncthreads();

    if (tid < 64) {
        float v = fmaxf(fmaxf(smax[0][tid], smax[1][tid]),
                        fmaxf(smax[2][tid], smax[3][tid])) + bias[tid];
        ssum[tid] = v;
    }
    __syncthreads();
    if (tid < 32) {
        float v = ssum[tid] + ssum[tid + 32];
#pragma unroll
        for (int o = 16; o > 0; o >>= 1)
            v += __shfl_down_sync(0xffffffffu, v, o);
        if (tid == 0) out[b] = v;
    }
}

extern "C" void kernel_launch(void* const* d_in, const int* in_sizes, int n_in,
                              void* d_out, int out_size) {
    const float* x    = (const float*)d_in[0];
    const float* w    = (const float*)d_in[1];
    const float* bias = (const float*)d_in[2];
    float* out = (float*)d_out;

    bf_pack_kernel<<<(125 * 4 * 4 * 32 + 255) / 256, 256>>>(w);
    fused_kernel<<<8000, 128>>>(x, bias, out);
}

// round 8
// speedup vs baseline: 2.8108x; 1.1521x over previous
#include <cuda_runtime.h>
#include <math.h>

#define CIN 32
#define COUT 64

// Weight B-fragments prepacked in mma.m16n8k8 layout with PERMUTED cin<->k map:
// within kc-block of 8 cins, k -> cin_phys = 2*(k&3) + (k>=4).
// [tap(125)][kc(4)][ntp(4)][lane(32)] uint4 = (b0,b1 @ n-tile 2ntp, b0,b1 @ 2ntp+1)
__device__ uint4 g_bf[125 * 4 * 4 * 32];

__device__ __forceinline__ unsigned f2tf32(float v) {
    unsigned u;
    asm("cvt.rna.tf32.f32 %0, %1;" : "=r"(u) : "f"(v));
    return u;
}

__global__ void bf_pack_kernel(const float* __restrict__ w) {
    int i = blockIdx.x * blockDim.x + threadIdx.x;
    if (i >= 125 * 4 * 4 * 32) return;
    int lane = i & 31, ntp = (i >> 5) & 3, kc = (i >> 7) & 3, tap = i >> 9;
    int k = lane & 3, n = lane >> 2;
    int cinA = kc * 8 + 2 * k;          // k       -> even member of pair
    int cinB = cinA + 1;                // k+4     -> odd member of pair
    int cout0 = (2 * ntp) * 8 + n, cout1 = cout0 + 8;
    uint4 o;
    o.x = f2tf32(w[(cinA * COUT + cout0) * 125 + tap]);
    o.y = f2tf32(w[(cinB * COUT + cout0) * 125 + tap]);
    o.z = f2tf32(w[(cinA * COUT + cout1) * 125 + tap]);
    o.w = f2tf32(w[(cinB * COUT + cout1) * 125 + tap]);
    g_bf[i] = o;
}

#define MMA(c0, c1, c2, c3, a0, a1, a2, a3, b0, b1)                              \
    asm("mma.sync.aligned.m16n8k8.row.col.f32.tf32.tf32.f32 "                    \
        "{%0,%1,%2,%3}, {%4,%5,%6,%7}, {%8,%9}, {%0,%1,%2,%3};"                  \
        : "+f"(c0), "+f"(c1), "+f"(c2), "+f"(c3)                                 \
        : "r"(a0), "r"(a1), "r"(a2), "r"(a3), "r"(b0), "r"(b1))

__device__ __forceinline__ int qoff(int pos) {      // pos in [0,27)
    int qd = pos / 9, qh = (pos / 3) % 3, qw = pos % 3;
    return qd * 25 + qh * 5 + qw;
}

// Patch layout: xs[w][pair(16)][pos(125)][2] floats; pair pc=kc*4+kb holds
// cins (8kc+2kb, 8kc+2kb+1) as (lo,hi) -> one LDS.64 per (a0,a2) / (a1,a3).
#define WSTRIDE 4000

__global__ __launch_bounds__(128)
void fused_kernel(const float* __restrict__ x,
                  const float* __restrict__ bias,
                  float* __restrict__ out)
{
    __shared__ float xs[2 * WSTRIDE];
    __shared__ float smax[2][4][64];
    __shared__ float ssum[4];

    const int tid  = threadIdx.x;       // 128 threads = 4 warps
    const int wid  = tid >> 5;
    const int lane = tid & 31;
    const int kb   = lane & 3;
    const int rr   = lane >> 2;

    const int b0 = blockIdx.x * 2;      // two windows per block

    // Stage both patches (tf32-rounded, paired-cin layout), zero-fill halo.
    for (int t = tid; t < 2 * 4000; t += 128) {
        const int w   = t >> 12;        // t/4096? NO -- use div
        const int tt  = t - w * 4096;   // placeholder; fixed below
        (void)tt;
        break;
    }
    // (proper staging loop)
    for (int t = tid; t < 8000; t += 128) {
        const int w  = t / 4000;
        const int rm = t - w * 4000;
        const int cin = rm / 125;
        const int q   = rm - cin * 125;
        const int bb  = b0 + w;
        const int n_  = bb / 500;
        const int r_  = bb % 500;
        const int odc = r_ / 100;
        const int ohc = (r_ / 10) % 10;
        const int owc = r_ % 10;
        const int dl = q / 25, hl = (q / 5) % 5, wl = q % 5;
        const int id = 3 * odc - 1 + dl;
        const int ih = 3 * ohc - 1 + hl;
        const int iw = 3 * owc - 1 + wl;
        float v = 0.f;
        if (id >= 0 && ih >= 0 && iw >= 0)
            v = x[(((n_ * CIN + cin) * 16 + id) << 10) + (ih << 5) + iw];
        xs[w * WSTRIDE + (cin >> 1) * 250 + q * 2 + (cin & 1)] = __uint_as_float(f2tf32(v));
    }
    __syncthreads();

    float rmax[2][8][2];
#pragma unroll
    for (int w = 0; w < 2; ++w)
#pragma unroll
        for (int nt = 0; nt < 8; ++nt) { rmax[w][nt][0] = -INFINITY; rmax[w][nt][1] = -INFINITY; }

    const int KD[2][3] = {{4, 2, 0}, {3, 1, 0}};
    const int NK[2]    = {3, 2};

#pragma unroll 1
    for (int s = 0; s < 4; ++s) {
        const int mi   = s * 4 + wid;   // 16 m-tiles: [class(8)][half(2)]
        const int cls  = mi >> 1;
        const int half = mi & 1;
        const int pd = (cls >> 2) & 1, ph = (cls >> 1) & 1, pw = cls & 1;

        const int pos0 = half * 16 + rr;        // < 27 always
        const int pos1 = pos0 + 8;
        const bool v1  = (pos1 < 27);
        const int qo0 = 2 * qoff(pos0);
        const int qo1 = v1 ? 2 * qoff(pos1) : 0;

        float c[2][8][4];
#pragma unroll
        for (int w = 0; w < 2; ++w)
#pragma unroll
            for (int nt = 0; nt < 8; ++nt)
#pragma unroll
                for (int j = 0; j < 4; ++j) c[w][nt][j] = 0.f;

#pragma unroll 1
        for (int ia = 0; ia < NK[pd]; ++ia) {
            const int kd = KD[pd][ia], jd = 2 - (kd >> 1);
#pragma unroll 1
            for (int ib = 0; ib < NK[ph]; ++ib) {
                const int kh = KD[ph][ib], jh = 2 - (kh >> 1);
#pragma unroll 1
                for (int ic = 0; ic < NK[pw]; ++ic) {
                    const int kw = KD[pw][ic], jw = 2 - (kw >> 1);
                    const int tap   = kd * 25 + kh * 5 + kw;
                    const int jofs2 = 2 * (jd * 25 + jh * 5 + jw);
                    const uint4* bp = g_bf + (tap * 16) * 32 + lane;
#pragma unroll
                    for (int kc = 0; kc < 4; ++kc) {
                        const int abase = (kc * 4 + kb) * 250 + jofs2;
                        const uint2 p00 = *(const uint2*)(xs + abase + qo0);             // w0 (a0,a2)
                        const uint2 p01 = *(const uint2*)(xs + abase + qo1);             // w0 (a1,a3)
                        const uint2 p10 = *(const uint2*)(xs + WSTRIDE + abase + qo0);   // w1
                        const uint2 p11 = *(const uint2*)(xs + WSTRIDE + abase + qo1);
#pragma unroll
                        for (int ntp = 0; ntp < 4; ++ntp) {
                            const uint4 B = bp[(kc * 4 + ntp) * 32];
                            MMA(c[0][2 * ntp][0], c[0][2 * ntp][1], c[0][2 * ntp][2], c[0][2 * ntp][3],
                                p00.x, p01.x, p00.y, p01.y, B.x, B.y);
                            MMA(c[0][2 * ntp + 1][0], c[0][2 * ntp + 1][1], c[0][2 * ntp + 1][2], c[0][2 * ntp + 1][3],
                                p00.x, p01.x, p00.y, p01.y, B.z, B.w);
                            MMA(c[1][2 * ntp][0], c[1][2 * ntp][1], c[1][2 * ntp][2], c[1][2 * ntp][3],
                                p10.x, p11.x, p10.y, p11.y, B.x, B.y);
                            MMA(c[1][2 * ntp + 1][0], c[1][2 * ntp + 1][1], c[1][2 * ntp + 1][2], c[1][2 * ntp + 1][3],
                                p10.x, p11.x, p10.y, p11.y, B.z, B.w);
                        }
                    }
                }
            }
        }

        // fold max-pool over this m-tile's positions (mask padded rows)
#pragma unroll
        for (int w = 0; w < 2; ++w)
#pragma unroll
            for (int nt = 0; nt < 8; ++nt) {
                rmax[w][nt][0] = fmaxf(rmax[w][nt][0], c[w][nt][0]);
                rmax[w][nt][1] = fmaxf(rmax[w][nt][1], c[w][nt][1]);
                if (v1) {
                    rmax[w][nt][0] = fmaxf(rmax[w][nt][0], c[w][nt][2]);
                    rmax[w][nt][1] = fmaxf(rmax[w][nt][1], c[w][nt][3]);
                }
            }
    }

    // reduce max across row-group lanes (same kb)
#pragma unroll
    for (int o = 4; o < 32; o <<= 1)
#pragma unroll
        for (int w = 0; w < 2; ++w)
#pragma unroll
            for (int nt = 0; nt < 8; ++nt) {
                rmax[w][nt][0] = fmaxf(rmax[w][nt][0], __shfl_xor_sync(0xffffffffu, rmax[w][nt][0], o));
                rmax[w][nt][1] = fmaxf(rmax[w][nt][1], __shfl_xor_sync(0xffffffffu, rmax[w][nt][1], o));
            }
    if (rr == 0) {
#pragma unroll
        for (int w = 0; w < 2; ++w)
#pragma unroll
            for (int nt = 0; nt < 8; ++nt) {
                smax[w][wid][nt * 8 + 2 * kb]     = rmax[w][nt][0];
                smax[w][wid][nt * 8 + 2 * kb + 1] = rmax[w][nt][1];
            }
    }
    __syncthreads();

    // tid 0..63 -> window 0, 64..127 -> window 1; cout = tid&63
    {
        const int w    = tid >> 6;
        const int cout = tid & 63;
        float v = fmaxf(fmaxf(smax[w][0][cout], smax[w][1][cout]),
                        fmaxf(smax[w][2][cout], smax[w][3][cout])) + bias[cout];
#pragma unroll
        for (int o = 16; o > 0; o >>= 1)
            v += __shfl_down_sync(0xffffffffu, v, o);
        if (lane == 0) ssum[tid >> 5] = v;
    }
    __syncthreads();
    if (tid == 0) {
        out[b0]     = ssum[0] + ssum[1];
        out[b0 + 1] = ssum[2] + ssum[3];
    }
}

extern "C" void kernel_launch(void* const* d_in, const int* in_sizes, int n_in,
                              void* d_out, int out_size) {
    const float* x    = (const float*)d_in[0];
    const float* w    = (const float*)d_in[1];
    const float* bias = (const float*)d_in[2];
    float* out = (float*)d_out;

    bf_pack_kernel<<<(125 * 4 * 4 * 32 + 255) / 256, 256>>>(w);
    fused_kernel<<<4000, 128>>>(x, bias, out);
}